// round 2
// baseline (speedup 1.0000x reference)
#include <cuda_runtime.h>
#include <cuda_bf16.h>

// HashEmbedding: out[t, d] = sum_{h=0..3} weight_table[x[t,h] + 513*h] * emb_table[x[t,h]>>1][d]
// NOTE: x is int32 (JAX downcasts the requested int64 without x64 enabled).
//
// Strategy: column-chunked smem-cached tables.
//   - gridDim.y = 4 column chunks of 64 floats each (D=256).
//   - Each block stages emb_table rows 0..255 for its 64-col slice (64 KB) and the
//     full weight table (8.2 KB) in dynamic shared memory, then streams tokens.
//   - 16 threads per token per chunk, each producing one float4 (coalesced STG.128).
//   - Grid 111x4 = 444 blocks = one full wave at 3 CTAs/SM; grid-stride over tiles.

#define NUM_HASHES 4
#define D 256
#define CH 64                  // columns per chunk
#define TPT (CH / 4)           // 16 threads per token (float4 each)
#define BLOCK_THREADS 512
#define TOK_PER_ITER (BLOCK_THREADS / TPT)   // 32 tokens per block-iteration
#define W_TABLE 2052           // 512*4 + 4
#define EMB_ROWS 256           // x in [0,512) -> idx = x>>1 in [0,256)
#define SMEM_FLOATS (EMB_ROWS * CH + W_TABLE)
#define SMEM_BYTES (SMEM_FLOATS * 4)

__global__ __launch_bounds__(BLOCK_THREADS, 3)
void hash_embedding_kernel(const int* __restrict__ x,
                           const float* __restrict__ weight_table,
                           const float* __restrict__ emb_table,
                           float* __restrict__ out,
                           int ntok)
{
    extern __shared__ float smem[];
    float* s_emb = smem;                      // [256][64]
    float* s_w   = smem + EMB_ROWS * CH;      // [2052]

    const int chunk = blockIdx.y;             // 0..3
    const int c0 = chunk * CH;

    // Stage embedding slice: 256 rows x 64 cols, float4 vectorized.
    // 4096 float4 total -> exactly 8 per thread.
    for (int i = threadIdx.x; i < EMB_ROWS * CH / 4; i += BLOCK_THREADS) {
        int r = i / (CH / 4);
        int c = (i % (CH / 4)) * 4;
        reinterpret_cast<float4*>(s_emb)[i] =
            *reinterpret_cast<const float4*>(emb_table + r * D + c0 + c);
    }
    // Stage weight table.
    for (int i = threadIdx.x; i < W_TABLE; i += BLOCK_THREADS) {
        s_w[i] = weight_table[i];
    }
    __syncthreads();

    const int grp  = threadIdx.x / TPT;       // token within iteration: 0..31
    const int lane = threadIdx.x % TPT;       // float4 slot within chunk: 0..15

    const int ntiles = ntok / TOK_PER_ITER;   // 2048 for 65536 tokens

    for (int tile = blockIdx.x; tile < ntiles; tile += gridDim.x) {
        const int t = tile * TOK_PER_ITER + grp;

        // Load this token's 4 hash indices: one aligned 128-bit load, broadcast
        // across the 16-lane group; hot in L2 across the 4 column chunks.
        const int4 xi = *reinterpret_cast<const int4*>(x + (long long)t * NUM_HASHES);
        const int i0 = xi.x, i1 = xi.y, i2 = xi.z, i3 = xi.w;

        // Per-sample weights: weight_idx = x + h * (K+1), K = 512.
        const float w0 = s_w[i0];
        const float w1 = s_w[i1 + 513];
        const float w2 = s_w[i2 + 1026];
        const float w3 = s_w[i3 + 1539];

        // Gather embedding slices (idx = x >> 1), conflict-free LDS.128.
        const float4 e0 = reinterpret_cast<const float4*>(s_emb + (i0 >> 1) * CH)[lane];
        const float4 e1 = reinterpret_cast<const float4*>(s_emb + (i1 >> 1) * CH)[lane];
        const float4 e2 = reinterpret_cast<const float4*>(s_emb + (i2 >> 1) * CH)[lane];
        const float4 e3 = reinterpret_cast<const float4*>(s_emb + (i3 >> 1) * CH)[lane];

        float4 r;
        r.x = w0 * e0.x + w1 * e1.x + w2 * e2.x + w3 * e3.x;
        r.y = w0 * e0.y + w1 * e1.y + w2 * e2.y + w3 * e3.y;
        r.z = w0 * e0.z + w1 * e1.z + w2 * e2.z + w3 * e3.z;
        r.w = w0 * e0.w + w1 * e1.w + w2 * e2.w + w3 * e3.w;

        *reinterpret_cast<float4*>(out + (long long)t * D + c0 + lane * 4) = r;
    }
}

extern "C" void kernel_launch(void* const* d_in, const int* in_sizes, int n_in,
                              void* d_out, int out_size)
{
    const int*   x            = (const int*)d_in[0];
    const float* weight_table = (const float*)d_in[1];
    const float* emb_table    = (const float*)d_in[2];
    float*       out          = (float*)d_out;

    const int ntok = in_sizes[0] / NUM_HASHES;   // 65536

    cudaFuncSetAttribute(hash_embedding_kernel,
                         cudaFuncAttributeMaxDynamicSharedMemorySize, SMEM_BYTES);

    dim3 grid(111, D / CH);   // 111 token-tile blocks x 4 column chunks = 444 = 3 CTAs x 148 SMs
    hash_embedding_kernel<<<grid, BLOCK_THREADS, SMEM_BYTES>>>(
        x, weight_table, emb_table, out, ntok);
}